// round 15
// baseline (speedup 1.0000x reference)
#include <cuda_runtime.h>
#include <cstdint>

// Problem dims
#define B_   512
#define T_   1024
#define D_   64
#define H_   256
#define O_   64
#define KTOT 320           // combined [x(64) | h(256)]

#define ROWS 4
#define NCTA (B_/ROWS)     // 128
#define NTHR 256
#define KSL  80            // k per kb-slice
#define VS4  84            // padded slice stride: kb bank-quads {0,5,2,7}
#define RSTR (4*VS4)       // 336 floats per row
#define VBUF (ROWS*RSTR)   // 1344 floats per buffer

// W chunk classes (20 chunks of 4 k per slice), ALL bf16
#define NCH_RF 14          // chunks 0..13  -> registers, bf16x4 (56 ull = 112 regs)
#define NCH_BM 6           // chunks 14..19 -> SMEM, bf16x4 (48 KB staged)

typedef unsigned long long ull;

__device__ ull        g_Wr[NCH_RF*4*NTHR];       // bf16x4 per (chunk, jj)
__device__ ulonglong2 g_Wsb[NCH_BM*2*NTHR];      // bf16x4 pairs: [chunk][jpair][tid]

__device__ __forceinline__ ull fma2(ull a, ull b, ull c) {
    ull d; asm("fma.rn.f32x2 %0, %1, %2, %3;" : "=l"(d) : "l"(a), "l"(b), "l"(c));
    return d;
}
// two bf16 in a 32-bit word -> packed f32x2 (PRMT expansion, alu pipe)
__device__ __forceinline__ ull bf2f2(unsigned w) {
    unsigned lo = __byte_perm(w, 0, 0x1044);   // f32 of halfword0
    unsigned hi = __byte_perm(w, 0, 0x3244);   // f32 of halfword1
    return ((ull)hi << 32) | lo;
}
__device__ __forceinline__ unsigned f2bf(float f) {   // RN-even bf16
    unsigned u = __float_as_uint(f);
    return (u + 0x7FFFu + ((u >> 16) & 1u)) >> 16;
}

// Pack Wf[H, D+H] into per-thread layouts. One prep thread per (chunk, jj, tid).
__global__ void ltc_prep(const float* __restrict__ Wf) {
    int idx = blockIdx.x * blockDim.x + threadIdx.x;
    if (idx >= 80*NTHR) return;
    int tid   = idx & (NTHR-1);
    int u2    = idx >> 8;            // 0..79
    int chunk = u2 >> 2, jj = u2 & 3;
    int lane = tid & 31;
    int kb   = lane & 3;
    int g    = (tid >> 5)*8 + (lane >> 2);   // 0..63
    int j    = g*4 + jj;
    int k0   = kb*KSL + chunk*4;
    const float* src = Wf + j*KTOT + k0;
    ull v = (ull)f2bf(src[0])
          | ((ull)f2bf(src[1]) << 16)
          | ((ull)f2bf(src[2]) << 32)
          | ((ull)f2bf(src[3]) << 48);
    if (chunk < NCH_RF) {
        g_Wr[(chunk*4 + jj)*NTHR + tid] = v;
    } else {
        int cc = chunk - NCH_RF;
        ((ull*)g_Wsb)[((cc*2 + (jj >> 1))*NTHR + tid)*2 + (jj & 1)] = v;
    }
}

// SMEM loop layout: s_wb 12*256 ulonglong2 (49152 B) | s_v 2*1344 floats (10752 B)
// SMEM proj layout: s_hl 1024 f | s_wo 64*260 f      (needs 70656 B total)
#define SM_V_F   (NCH_BM*2*NTHR*4)           // float offset of s_v = 12288
#define SM_TOT_B ((1024 + 64*260)*4)         // 70,656 B (covers both layouts)

__global__ __launch_bounds__(NTHR, 1)
void ltc_main(const float* __restrict__ x,
              const float* __restrict__ bf,
              const float* __restrict__ tau,
              const float* __restrict__ A,
              const float* __restrict__ Wo,
              const float* __restrict__ bo,
              float* __restrict__ out)
{
    extern __shared__ float sm[];
    ulonglong2* s_wb = (ulonglong2*)sm;
    float*      s_v  = sm + SM_V_F;

    const int tid  = threadIdx.x;
    const int lane = tid & 31;
    const int kb   = lane & 3;
    const bool p1  = kb & 1;
    const bool p2  = kb & 2;
    const int g    = (tid >> 5)*8 + (lane >> 2);  // 0..63
    const int j0   = g*4;
    const int row0 = blockIdx.x * ROWS;

    // ---- stage bf16 SMEM-W (coalesced) ----
    for (int e = 0; e < NCH_BM*2; e++) s_wb[e*NTHR + tid] = g_Wsb[e*NTHR + tid];

    // ---- W registers (56 ull = 112 regs, bf16x4 each) ----
    ull wr[NCH_RF*4];
#pragma unroll
    for (int p = 0; p < NCH_RF*4; p++) wr[p] = g_Wr[p*NTHR + tid];

    // ---- gate constants for owned j's (j0..j0+3); this thread updates row kb ----
    const float4 bf4  = *(const float4*)(bf  + j0);
    const float4 tau4 = *(const float4*)(tau + j0);
    const float4 A4   = *(const float4*)(A   + j0);
    const float it4x = expf(-tau4.x), it4y = expf(-tau4.y),
                it4z = expf(-tau4.z), it4w = expf(-tau4.w);
    float hst[4] = {0.f, 0.f, 0.f, 0.f};
    const int hbase = ((64 + j0)/KSL)*VS4 + (64 + j0) % KSL;  // 4-span never crosses slice

    // ---- x writer: each thread owns one (row, d) ----
    const int xr = tid >> 6, xd = tid & 63;
    const float* xptr = x + (size_t)(row0 + xr) * T_ * D_ + xd;

    // ---- init v buffer 0 ----
    for (int i = tid; i < 2*VBUF; i += NTHR) s_v[i] = 0.f;
    __syncthreads();
    s_v[xr*RSTR + xd] = xptr[0];
    __syncthreads();

    // ================= recurrent loop =================
#pragma unroll 2
    for (int t = 0; t < T_; ++t) {
        const float* vb = s_v + (t & 1)*VBUF;
        float*       vn = s_v + ((t + 1) & 1)*VBUF;
        const float* vbk = vb + kb*VS4;

        float x_pre = (t + 1 < T_) ? xptr[(t + 1) * D_] : 0.f;

        ull acc[16];
#pragma unroll
        for (int i = 0; i < 16; i++) acc[i] = 0ull;

#define CH_FMA(W0,W1,W2,W3)                                                \
        {                                                                  \
            ulonglong2 v0 = *(const ulonglong2*)(vbk + 0*RSTR + q*4);      \
            ulonglong2 v1 = *(const ulonglong2*)(vbk + 1*RSTR + q*4);      \
            ulonglong2 v2 = *(const ulonglong2*)(vbk + 2*RSTR + q*4);      \
            ulonglong2 v3 = *(const ulonglong2*)(vbk + 3*RSTR + q*4);      \
            acc[ 0]=fma2(W0.x,v0.x,acc[ 0]); acc[ 0]=fma2(W0.y,v0.y,acc[ 0]); \
            acc[ 1]=fma2(W0.x,v1.x,acc[ 1]); acc[ 1]=fma2(W0.y,v1.y,acc[ 1]); \
            acc[ 2]=fma2(W0.x,v2.x,acc[ 2]); acc[ 2]=fma2(W0.y,v2.y,acc[ 2]); \
            acc[ 3]=fma2(W0.x,v3.x,acc[ 3]); acc[ 3]=fma2(W0.y,v3.y,acc[ 3]); \
            acc[ 4]=fma2(W1.x,v0.x,acc[ 4]); acc[ 4]=fma2(W1.y,v0.y,acc[ 4]); \
            acc[ 5]=fma2(W1.x,v1.x,acc[ 5]); acc[ 5]=fma2(W1.y,v1.y,acc[ 5]); \
            acc[ 6]=fma2(W1.x,v2.x,acc[ 6]); acc[ 6]=fma2(W1.y,v2.y,acc[ 6]); \
            acc[ 7]=fma2(W1.x,v3.x,acc[ 7]); acc[ 7]=fma2(W1.y,v3.y,acc[ 7]); \
            acc[ 8]=fma2(W2.x,v0.x,acc[ 8]); acc[ 8]=fma2(W2.y,v0.y,acc[ 8]); \
            acc[ 9]=fma2(W2.x,v1.x,acc[ 9]); acc[ 9]=fma2(W2.y,v1.y,acc[ 9]); \
            acc[10]=fma2(W2.x,v2.x,acc[10]); acc[10]=fma2(W2.y,v2.y,acc[10]); \
            acc[11]=fma2(W2.x,v3.x,acc[11]); acc[11]=fma2(W2.y,v3.y,acc[11]); \
            acc[12]=fma2(W3.x,v0.x,acc[12]); acc[12]=fma2(W3.y,v0.y,acc[12]); \
            acc[13]=fma2(W3.x,v1.x,acc[13]); acc[13]=fma2(W3.y,v1.y,acc[13]); \
            acc[14]=fma2(W3.x,v2.x,acc[14]); acc[14]=fma2(W3.y,v2.y,acc[14]); \
            acc[15]=fma2(W3.x,v3.x,acc[15]); acc[15]=fma2(W3.y,v3.y,acc[15]); \
        }

        // ---- chunks 0..13: W from registers (bf16x4 -> f32x2 via PRMT) ----
#pragma unroll
        for (int q = 0; q < NCH_RF; q++) {
            ull r0 = wr[q*4+0], r1 = wr[q*4+1], r2 = wr[q*4+2], r3 = wr[q*4+3];
            ulonglong2 W0 = make_ulonglong2(bf2f2((unsigned)r0), bf2f2((unsigned)(r0 >> 32)));
            ulonglong2 W1 = make_ulonglong2(bf2f2((unsigned)r1), bf2f2((unsigned)(r1 >> 32)));
            ulonglong2 W2 = make_ulonglong2(bf2f2((unsigned)r2), bf2f2((unsigned)(r2 >> 32)));
            ulonglong2 W3 = make_ulonglong2(bf2f2((unsigned)r3), bf2f2((unsigned)(r3 >> 32)));
            CH_FMA(W0, W1, W2, W3);
        }

        // ---- chunks 14..19: W from SMEM (bf16x4 -> f32x2 via PRMT) ----
#pragma unroll
        for (int q = NCH_RF; q < 20; q++) {
            const int cc = q - NCH_RF;
            ulonglong2 e0 = s_wb[(cc*2 + 0)*NTHR + tid];  // jj0 (.x), jj1 (.y)
            ulonglong2 e1 = s_wb[(cc*2 + 1)*NTHR + tid];  // jj2 (.x), jj3 (.y)
            ulonglong2 W0 = make_ulonglong2(bf2f2((unsigned)e0.x), bf2f2((unsigned)(e0.x >> 32)));
            ulonglong2 W1 = make_ulonglong2(bf2f2((unsigned)e0.y), bf2f2((unsigned)(e0.y >> 32)));
            ulonglong2 W2 = make_ulonglong2(bf2f2((unsigned)e1.x), bf2f2((unsigned)(e1.x >> 32)));
            ulonglong2 W3 = make_ulonglong2(bf2f2((unsigned)e1.y), bf2f2((unsigned)(e1.y >> 32)));
            CH_FMA(W0, W1, W2, W3);
        }
#undef CH_FMA

        // ---- collapse packed halves (fma pipe), then f32 quad reduce (12 SHFL.32) ----
        float zs[16];
#pragma unroll
        for (int i = 0; i < 16; i++)
            zs[i] = __uint_as_float((unsigned)acc[i])
                  + __uint_as_float((unsigned)(acc[i] >> 32));

        float zv[4];
#pragma unroll
        for (int jj = 0; jj < 4; jj++) {
            const int Ai = jj*4;
            float s0 = p1 ? zs[Ai+0] : zs[Ai+1];
            float s1 = p1 ? zs[Ai+2] : zs[Ai+3];
            float r0 = __shfl_xor_sync(0xFFFFFFFFu, s0, 1);
            float r1 = __shfl_xor_sync(0xFFFFFFFFu, s1, 1);
            float u  = (p1 ? zs[Ai+1] : zs[Ai+0]) + r0;     // row p1 over lane pair
            float w  = (p1 ? zs[Ai+3] : zs[Ai+2]) + r1;     // row 2+p1 over lane pair
            float s2 = p2 ? u : w;
            float r2 = __shfl_xor_sync(0xFFFFFFFFu, s2, 2);
            zv[jj] = (p2 ? w : u) + r2;                     // row kb, all 4 lanes
        }

        // ---- gate + state update (this thread: j0..j0+3, row = kb) ----
        {
            float f0 = __fdividef(1.f, 1.f + __expf(-(zv[0] + bf4.x)));
            float f1 = __fdividef(1.f, 1.f + __expf(-(zv[1] + bf4.y)));
            float f2 = __fdividef(1.f, 1.f + __expf(-(zv[2] + bf4.z)));
            float f3 = __fdividef(1.f, 1.f + __expf(-(zv[3] + bf4.w)));
            hst[0] += (-(it4x + f0)*hst[0] + f0*A4.x) * 0.1f;
            hst[1] += (-(it4y + f1)*hst[1] + f1*A4.y) * 0.1f;
            hst[2] += (-(it4z + f2)*hst[2] + f2*A4.z) * 0.1f;
            hst[3] += (-(it4w + f3)*hst[3] + f3*A4.w) * 0.1f;
            *(float4*)(vn + kb*RSTR + hbase) = make_float4(hst[0], hst[1], hst[2], hst[3]);
            vn[xr*RSTR + xd] = x_pre;
        }
        __syncthreads();
    }

    // ================= output projection =================
    // h_final: thread (g,kb) holds rows=kb for j0..j0+3.
    float* s_hl = (float*)sm;                 // [r][j], 1024 floats (reuse W region)
    float* s_wo = (float*)sm + 1024;          // [o][260]
    __syncthreads();
    *(float4*)(s_hl + kb*256 + j0) = make_float4(hst[0], hst[1], hst[2], hst[3]);
    for (int i = tid; i < 64*256; i += NTHR) {
        int o = i >> 8, q = i & 255;
        s_wo[o*260 + q] = Wo[i];
    }
    __syncthreads();

    {
        int r = tid >> 6, o = tid & 63;
        const float4* w4 = (const float4*)(s_wo + o*260);
        const float4* h4 = (const float4*)(s_hl + r*256);
        float s = bo[o];
#pragma unroll
        for (int q = 0; q < 64; q++) {
            float4 w = w4[q];
            float4 h = h4[q];
            s += w.x*h.x + w.y*h.y + w.z*h.z + w.w*h.w;
        }
        out[(row0 + r)*O_ + o] = s;
    }
}

extern "C" void kernel_launch(void* const* d_in, const int* in_sizes, int n_in,
                              void* d_out, int out_size)
{
    (void)in_sizes; (void)n_in; (void)out_size;
    const float* x   = (const float*)d_in[0];
    const float* Wf  = (const float*)d_in[1];
    const float* bf  = (const float*)d_in[2];
    const float* tau = (const float*)d_in[3];
    const float* A   = (const float*)d_in[4];
    const float* Wo  = (const float*)d_in[5];
    const float* bo  = (const float*)d_in[6];
    float* out = (float*)d_out;

    const int smem_bytes = SM_TOT_B;       // 70,656 B
    cudaFuncSetAttribute(ltc_main,
                         cudaFuncAttributeMaxDynamicSharedMemorySize, smem_bytes);

    ltc_prep<<<(80*NTHR + NTHR - 1) / NTHR, NTHR>>>(Wf);
    ltc_main<<<NCTA, NTHR, smem_bytes>>>(x, bf, tau, A, Wo, bo, out);
}

// round 16
// speedup vs baseline: 1.2996x; 1.2996x over previous
#include <cuda_runtime.h>
#include <cstdint>

// Problem dims
#define B_   512
#define T_   1024
#define D_   64
#define H_   256
#define O_   64
#define KTOT 320           // combined [x(64) | h(256)]

#define ROWS 4
#define NCTA (B_/ROWS)     // 128
#define NTHR 256
#define KSL  80            // k per kb-slice
#define VS4  84            // padded slice stride: kb bank-quads {0,5,2,7}
#define RSTR (4*VS4)       // 336 floats per row
#define VBUF (ROWS*RSTR)   // 1344 floats per buffer

// W chunk classes (20 chunks of 4 k per slice)
#define NCH_RF 7           // chunks 0..6   -> registers, fp32 (56 ull = 112 regs)
#define NCH_BM 13          // chunks 7..19  -> SMEM, bf16x4 (104 KB staged)

typedef unsigned long long ull;

__device__ ull        g_Wr[NCH_RF*4*2*NTHR];     // fp32 pairs
__device__ ulonglong2 g_Wsb[NCH_BM*2*NTHR];      // bf16x4 pairs: [chunk][jpair][tid]

__device__ __forceinline__ ull fma2(ull a, ull b, ull c) {
    ull d; asm("fma.rn.f32x2 %0, %1, %2, %3;" : "=l"(d) : "l"(a), "l"(b), "l"(c));
    return d;
}
// two bf16 in a 32-bit word -> packed f32x2 (PRMT expansion, alu pipe)
__device__ __forceinline__ ull bf2f2(unsigned w) {
    unsigned lo = __byte_perm(w, 0, 0x1044);   // f32 of halfword0
    unsigned hi = __byte_perm(w, 0, 0x3244);   // f32 of halfword1
    return ((ull)hi << 32) | lo;
}
__device__ __forceinline__ unsigned f2bf(float f) {   // RN-even bf16
    unsigned u = __float_as_uint(f);
    return (u + 0x7FFFu + ((u >> 16) & 1u)) >> 16;
}

// Pack Wf[H, D+H] into per-thread layouts. One prep thread per (chunk, jj, tid).
__global__ void ltc_prep(const float* __restrict__ Wf) {
    int idx = blockIdx.x * blockDim.x + threadIdx.x;
    if (idx >= 80*NTHR) return;
    int tid   = idx & (NTHR-1);
    int u2    = idx >> 8;            // 0..79
    int chunk = u2 >> 2, jj = u2 & 3;
    int lane = tid & 31;
    int kb   = lane & 3;
    int g    = (tid >> 5)*8 + (lane >> 2);   // 0..63
    int j    = g*4 + jj;
    int k0   = kb*KSL + chunk*4;
    const float* src = Wf + j*KTOT + k0;
    if (chunk < NCH_RF) {
        ull lo = ((ull)__float_as_uint(src[1]) << 32) | __float_as_uint(src[0]);
        ull hi = ((ull)__float_as_uint(src[3]) << 32) | __float_as_uint(src[2]);
        int p = (chunk*4 + jj)*2;
        g_Wr[(p+0)*NTHR + tid] = lo;
        g_Wr[(p+1)*NTHR + tid] = hi;
    } else {
        ull v = (ull)f2bf(src[0])
              | ((ull)f2bf(src[1]) << 16)
              | ((ull)f2bf(src[2]) << 32)
              | ((ull)f2bf(src[3]) << 48);
        int cc = chunk - NCH_RF;
        ((ull*)g_Wsb)[((cc*2 + (jj >> 1))*NTHR + tid)*2 + (jj & 1)] = v;
    }
}

// SMEM: s_wb 26*256 ulonglong2 (106,496 B) | s_v 2*1344 floats (10,752 B)
#define SM_V_F   (NCH_BM*2*NTHR*4)           // float offset of s_v = 26624
#define SM_TOT_B ((SM_V_F + 2*VBUF)*4)       // 117,248 B

__global__ __launch_bounds__(NTHR, 1)
void ltc_main(const float* __restrict__ x,
              const float* __restrict__ bf,
              const float* __restrict__ tau,
              const float* __restrict__ A,
              const float* __restrict__ Wo,
              const float* __restrict__ bo,
              float* __restrict__ out)
{
    extern __shared__ float sm[];
    ulonglong2* s_wb = (ulonglong2*)sm;
    float*      s_v  = sm + SM_V_F;

    const int tid  = threadIdx.x;
    const int lane = tid & 31;
    const int kb   = lane & 3;
    const bool p1  = kb & 1;
    const bool p2  = kb & 2;
    const int g    = (tid >> 5)*8 + (lane >> 2);  // 0..63
    const int j0   = g*4;
    const int row0 = blockIdx.x * ROWS;

    // ---- stage bf16 SMEM-W (coalesced) ----
    for (int e = 0; e < NCH_BM*2; e++) s_wb[e*NTHR + tid] = g_Wsb[e*NTHR + tid];

    // ---- W registers (56 ull = 112 regs, fp32 pairs) ----
    ull wr[56];
#pragma unroll
    for (int p = 0; p < 56; p++) wr[p] = g_Wr[p*NTHR + tid];

    // ---- gate constants for owned j's (j0..j0+3); this thread updates row kb ----
    const float4 bf4  = *(const float4*)(bf  + j0);
    const float4 tau4 = *(const float4*)(tau + j0);
    const float4 A4   = *(const float4*)(A   + j0);
    const float it4x = expf(-tau4.x), it4y = expf(-tau4.y),
                it4z = expf(-tau4.z), it4w = expf(-tau4.w);
    float hst[4] = {0.f, 0.f, 0.f, 0.f};
    const int hbase = ((64 + j0)/KSL)*VS4 + (64 + j0) % KSL;  // 4-span never crosses slice

    // ---- x writer: each thread owns one (row, d) ----
    const int xr = tid >> 6, xd = tid & 63;
    const float* xptr = x + (size_t)(row0 + xr) * T_ * D_ + xd;

    // ---- init v buffer 0 ----
    for (int i = tid; i < 2*VBUF; i += NTHR) s_v[i] = 0.f;
    __syncthreads();
    s_v[xr*RSTR + xd] = xptr[0];
    __syncthreads();

    // ================= recurrent loop =================
    for (int t = 0; t < T_; ++t) {
        const float* vb = s_v + (t & 1)*VBUF;
        float*       vn = s_v + ((t + 1) & 1)*VBUF;
        const float* vbk = vb + kb*VS4;

        float x_pre = (t + 1 < T_) ? xptr[(t + 1) * D_] : 0.f;

        ull acc[16];
#pragma unroll
        for (int i = 0; i < 16; i++) acc[i] = 0ull;

#define CH_FMA(W0,W1,W2,W3)                                                \
        {                                                                  \
            ulonglong2 v0 = *(const ulonglong2*)(vbk + 0*RSTR + q*4);      \
            ulonglong2 v1 = *(const ulonglong2*)(vbk + 1*RSTR + q*4);      \
            ulonglong2 v2 = *(const ulonglong2*)(vbk + 2*RSTR + q*4);      \
            ulonglong2 v3 = *(const ulonglong2*)(vbk + 3*RSTR + q*4);      \
            acc[ 0]=fma2(W0.x,v0.x,acc[ 0]); acc[ 0]=fma2(W0.y,v0.y,acc[ 0]); \
            acc[ 1]=fma2(W0.x,v1.x,acc[ 1]); acc[ 1]=fma2(W0.y,v1.y,acc[ 1]); \
            acc[ 2]=fma2(W0.x,v2.x,acc[ 2]); acc[ 2]=fma2(W0.y,v2.y,acc[ 2]); \
            acc[ 3]=fma2(W0.x,v3.x,acc[ 3]); acc[ 3]=fma2(W0.y,v3.y,acc[ 3]); \
            acc[ 4]=fma2(W1.x,v0.x,acc[ 4]); acc[ 4]=fma2(W1.y,v0.y,acc[ 4]); \
            acc[ 5]=fma2(W1.x,v1.x,acc[ 5]); acc[ 5]=fma2(W1.y,v1.y,acc[ 5]); \
            acc[ 6]=fma2(W1.x,v2.x,acc[ 6]); acc[ 6]=fma2(W1.y,v2.y,acc[ 6]); \
            acc[ 7]=fma2(W1.x,v3.x,acc[ 7]); acc[ 7]=fma2(W1.y,v3.y,acc[ 7]); \
            acc[ 8]=fma2(W2.x,v0.x,acc[ 8]); acc[ 8]=fma2(W2.y,v0.y,acc[ 8]); \
            acc[ 9]=fma2(W2.x,v1.x,acc[ 9]); acc[ 9]=fma2(W2.y,v1.y,acc[ 9]); \
            acc[10]=fma2(W2.x,v2.x,acc[10]); acc[10]=fma2(W2.y,v2.y,acc[10]); \
            acc[11]=fma2(W2.x,v3.x,acc[11]); acc[11]=fma2(W2.y,v3.y,acc[11]); \
            acc[12]=fma2(W3.x,v0.x,acc[12]); acc[12]=fma2(W3.y,v0.y,acc[12]); \
            acc[13]=fma2(W3.x,v1.x,acc[13]); acc[13]=fma2(W3.y,v1.y,acc[13]); \
            acc[14]=fma2(W3.x,v2.x,acc[14]); acc[14]=fma2(W3.y,v2.y,acc[14]); \
            acc[15]=fma2(W3.x,v3.x,acc[15]); acc[15]=fma2(W3.y,v3.y,acc[15]); \
        }

        // ---- chunks 0..6: W from registers (fp32, no unpack temps) ----
#pragma unroll
        for (int q = 0; q < NCH_RF; q++) {
            ulonglong2 W0 = make_ulonglong2(wr[(q*4+0)*2], wr[(q*4+0)*2+1]);
            ulonglong2 W1 = make_ulonglong2(wr[(q*4+1)*2], wr[(q*4+1)*2+1]);
            ulonglong2 W2 = make_ulonglong2(wr[(q*4+2)*2], wr[(q*4+2)*2+1]);
            ulonglong2 W3 = make_ulonglong2(wr[(q*4+3)*2], wr[(q*4+3)*2+1]);
            CH_FMA(W0, W1, W2, W3);
        }

        // ---- chunks 7..19: W from SMEM (bf16x4 -> f32x2 via PRMT) ----
#pragma unroll
        for (int q = NCH_RF; q < 20; q++) {
            const int cc = q - NCH_RF;
            ulonglong2 e0 = s_wb[(cc*2 + 0)*NTHR + tid];  // jj0 (.x), jj1 (.y)
            ulonglong2 e1 = s_wb[(cc*2 + 1)*NTHR + tid];  // jj2 (.x), jj3 (.y)
            ulonglong2 W0 = make_ulonglong2(bf2f2((unsigned)e0.x), bf2f2((unsigned)(e0.x >> 32)));
            ulonglong2 W1 = make_ulonglong2(bf2f2((unsigned)e0.y), bf2f2((unsigned)(e0.y >> 32)));
            ulonglong2 W2 = make_ulonglong2(bf2f2((unsigned)e1.x), bf2f2((unsigned)(e1.x >> 32)));
            ulonglong2 W3 = make_ulonglong2(bf2f2((unsigned)e1.y), bf2f2((unsigned)(e1.y >> 32)));
            CH_FMA(W0, W1, W2, W3);
        }
#undef CH_FMA

        // ---- collapse packed halves (fma pipe), then f32 quad reduce (12 SHFL.32) ----
        float zs[16];
#pragma unroll
        for (int i = 0; i < 16; i++)
            zs[i] = __uint_as_float((unsigned)acc[i])
                  + __uint_as_float((unsigned)(acc[i] >> 32));

        float zv[4];
#pragma unroll
        for (int jj = 0; jj < 4; jj++) {
            const int Ai = jj*4;
            float s0 = p1 ? zs[Ai+0] : zs[Ai+1];
            float s1 = p1 ? zs[Ai+2] : zs[Ai+3];
            float r0 = __shfl_xor_sync(0xFFFFFFFFu, s0, 1);
            float r1 = __shfl_xor_sync(0xFFFFFFFFu, s1, 1);
            float u  = (p1 ? zs[Ai+1] : zs[Ai+0]) + r0;     // row p1 over lane pair
            float w  = (p1 ? zs[Ai+3] : zs[Ai+2]) + r1;     // row 2+p1 over lane pair
            float s2 = p2 ? u : w;
            float r2 = __shfl_xor_sync(0xFFFFFFFFu, s2, 2);
            zv[jj] = (p2 ? w : u) + r2;                     // row kb, all 4 lanes
        }

        // ---- gate + state update (this thread: j0..j0+3, row = kb) ----
        {
            float f0 = __fdividef(1.f, 1.f + __expf(-(zv[0] + bf4.x)));
            float f1 = __fdividef(1.f, 1.f + __expf(-(zv[1] + bf4.y)));
            float f2 = __fdividef(1.f, 1.f + __expf(-(zv[2] + bf4.z)));
            float f3 = __fdividef(1.f, 1.f + __expf(-(zv[3] + bf4.w)));
            hst[0] += (-(it4x + f0)*hst[0] + f0*A4.x) * 0.1f;
            hst[1] += (-(it4y + f1)*hst[1] + f1*A4.y) * 0.1f;
            hst[2] += (-(it4z + f2)*hst[2] + f2*A4.z) * 0.1f;
            hst[3] += (-(it4w + f3)*hst[3] + f3*A4.w) * 0.1f;
            *(float4*)(vn + kb*RSTR + hbase) = make_float4(hst[0], hst[1], hst[2], hst[3]);
            vn[xr*RSTR + xd] = x_pre;
        }
        __syncthreads();
    }

    // ================= output projection =================
    // h_final: thread (g,kb) holds rows=kb for j0..j0+3.
    float* s_hl = (float*)sm;                 // [r][j], 1024 floats (reuse W region)
    float* s_wo = (float*)sm + 1024;          // [o][260]
    *(float4*)(s_hl + kb*256 + j0) = make_float4(hst[0], hst[1], hst[2], hst[3]);
    for (int i = tid; i < 64*256; i += NTHR) {
        int o = i >> 8, q = i & 255;
        s_wo[o*260 + q] = Wo[i];
    }
    __syncthreads();

    {
        int r = tid >> 6, o = tid & 63;
        const float4* w4 = (const float4*)(s_wo + o*260);
        const float4* h4 = (const float4*)(s_hl + r*256);
        float s = bo[o];
#pragma unroll
        for (int q = 0; q < 64; q++) {
            float4 w = w4[q];
            float4 h = h4[q];
            s += w.x*h.x + w.y*h.y + w.z*h.z + w.w*h.w;
        }
        out[(row0 + r)*O_ + o] = s;
    }
}

extern "C" void kernel_launch(void* const* d_in, const int* in_sizes, int n_in,
                              void* d_out, int out_size)
{
    (void)in_sizes; (void)n_in; (void)out_size;
    const float* x   = (const float*)d_in[0];
    const float* Wf  = (const float*)d_in[1];
    const float* bf  = (const float*)d_in[2];
    const float* tau = (const float*)d_in[3];
    const float* A   = (const float*)d_in[4];
    const float* Wo  = (const float*)d_in[5];
    const float* bo  = (const float*)d_in[6];
    float* out = (float*)d_out;

    const int smem_bytes = SM_TOT_B;       // 117,248 B
    cudaFuncSetAttribute(ltc_main,
                         cudaFuncAttributeMaxDynamicSharedMemorySize, smem_bytes);

    ltc_prep<<<(80*NTHR + NTHR - 1) / NTHR, NTHR>>>(Wf);
    ltc_main<<<NCTA, NTHR, smem_bytes>>>(x, bf, tau, A, Wo, bo, out);
}